// round 2
// baseline (speedup 1.0000x reference)
#include <cuda_runtime.h>
#include <math.h>

#define BB 4
#define CC 512
#define NN 4096   // H*W = 64*64
#define DD 512

// Scratch: __device__ globals (no allocation allowed in kernel_launch)
__device__ float g_QKV[3][(size_t)BB * NN * DD];          // Q, K, V  (token-major: [b][t][d])
__device__ float g_S[(size_t)BB * NN * NN];               // attention matrix

#define SCALE 0.04419417382415922f   // 1/sqrt(512)

// ---------------------------------------------------------------------------
// QKV projection: out[b][t][d] = sum_c X[b][c][t] * W[d][c]
// X is x viewed as (B, C, N); W is (D, C) row-major.
// Tile: 64 (t) x 64 (d), k-chunk 16 over c. 256 threads, 4x4 micro-tile.
// ---------------------------------------------------------------------------
__global__ __launch_bounds__(256) void qkv_kernel(
    const float* __restrict__ x,
    const float* __restrict__ Wq,
    const float* __restrict__ Wk,
    const float* __restrict__ Wv)
{
    int b     = blockIdx.z / 3;
    int which = blockIdx.z % 3;
    const float* W = (which == 0) ? Wq : ((which == 1) ? Wk : Wv);
    float* out = &g_QKV[which][(size_t)b * NN * DD];
    const float* X = x + (size_t)b * CC * NN;

    __shared__ float Xs[16][64 + 1];  // [cc][tt]
    __shared__ float Ws[16][64 + 1];  // [cc][dd]

    int t0 = blockIdx.x * 64;
    int d0 = blockIdx.y * 64;
    int tid = threadIdx.x;
    int tx = tid % 16;   // d micro index
    int ty = tid / 16;   // t micro index

    float acc[4][4] = {};

    for (int c0 = 0; c0 < CC; c0 += 16) {
        // Xs[cc][tt] <- X[(c0+cc)*NN + t0+tt]   (contiguous in t)
        {
            int f  = tid * 4;
            int cc = f / 64;
            int tt = f % 64;
            float4 v = *(const float4*)&X[(size_t)(c0 + cc) * NN + t0 + tt];
            Xs[cc][tt + 0] = v.x; Xs[cc][tt + 1] = v.y;
            Xs[cc][tt + 2] = v.z; Xs[cc][tt + 3] = v.w;
        }
        // Ws[cc][dd] <- W[(d0+dd)*CC + c0+cc]   (contiguous in c)
        {
            int dd = tid / 4;
            int cc = (tid % 4) * 4;
            float4 v = *(const float4*)&W[(size_t)(d0 + dd) * CC + c0 + cc];
            Ws[cc + 0][dd] = v.x; Ws[cc + 1][dd] = v.y;
            Ws[cc + 2][dd] = v.z; Ws[cc + 3][dd] = v.w;
        }
        __syncthreads();

        #pragma unroll
        for (int kk = 0; kk < 16; kk++) {
            float a[4], w[4];
            #pragma unroll
            for (int u = 0; u < 4; u++) a[u] = Xs[kk][ty * 4 + u];
            #pragma unroll
            for (int v = 0; v < 4; v++) w[v] = Ws[kk][tx * 4 + v];
            #pragma unroll
            for (int u = 0; u < 4; u++)
                #pragma unroll
                for (int v = 0; v < 4; v++)
                    acc[u][v] += a[u] * w[v];
        }
        __syncthreads();
    }

    #pragma unroll
    for (int u = 0; u < 4; u++) {
        float4 r = make_float4(acc[u][0], acc[u][1], acc[u][2], acc[u][3]);
        *(float4*)&out[(size_t)(t0 + ty * 4 + u) * DD + d0 + tx * 4] = r;
    }
}

// ---------------------------------------------------------------------------
// S[b][i][j] = SCALE * sum_d Q[b][i][d] * K[b][j][d]
// Tile 64(i) x 64(j), k-chunk 16 over d.
// ---------------------------------------------------------------------------
__global__ __launch_bounds__(256) void s_kernel()
{
    int b = blockIdx.z;
    const float* Q = &g_QKV[0][(size_t)b * NN * DD];
    const float* K = &g_QKV[1][(size_t)b * NN * DD];
    float* S = g_S + (size_t)b * NN * NN;

    __shared__ float Qs[16][64 + 1];  // [kk][ii]
    __shared__ float Ks[16][64 + 1];  // [kk][jj]

    int i0 = blockIdx.x * 64;
    int j0 = blockIdx.y * 64;
    int tid = threadIdx.x;
    int tx = tid % 16;   // j micro
    int ty = tid / 16;   // i micro

    float acc[4][4] = {};

    for (int d0 = 0; d0 < DD; d0 += 16) {
        // Qs[kk][ii] <- Q[(i0+ii)*DD + d0+kk]  (contiguous over kk)
        {
            int ii = tid / 4;
            int kk = (tid % 4) * 4;
            float4 v = *(const float4*)&Q[(size_t)(i0 + ii) * DD + d0 + kk];
            Qs[kk + 0][ii] = v.x; Qs[kk + 1][ii] = v.y;
            Qs[kk + 2][ii] = v.z; Qs[kk + 3][ii] = v.w;
        }
        {
            int jj = tid / 4;
            int kk = (tid % 4) * 4;
            float4 v = *(const float4*)&K[(size_t)(j0 + jj) * DD + d0 + kk];
            Ks[kk + 0][jj] = v.x; Ks[kk + 1][jj] = v.y;
            Ks[kk + 2][jj] = v.z; Ks[kk + 3][jj] = v.w;
        }
        __syncthreads();

        #pragma unroll
        for (int kk = 0; kk < 16; kk++) {
            float a[4], c[4];
            #pragma unroll
            for (int u = 0; u < 4; u++) a[u] = Qs[kk][ty * 4 + u];
            #pragma unroll
            for (int v = 0; v < 4; v++) c[v] = Ks[kk][tx * 4 + v];
            #pragma unroll
            for (int u = 0; u < 4; u++)
                #pragma unroll
                for (int v = 0; v < 4; v++)
                    acc[u][v] += a[u] * c[v];
        }
        __syncthreads();
    }

    #pragma unroll
    for (int u = 0; u < 4; u++) {
        float4 r = make_float4(acc[u][0] * SCALE, acc[u][1] * SCALE,
                               acc[u][2] * SCALE, acc[u][3] * SCALE);
        *(float4*)&S[(size_t)(i0 + ty * 4 + u) * NN + j0 + tx * 4] = r;
    }
}

// ---------------------------------------------------------------------------
// In-place row softmax over S. One block per row (N=4096, 256 thr, 16/thread).
// ---------------------------------------------------------------------------
__global__ __launch_bounds__(256) void softmax_kernel()
{
    __shared__ float red[256];
    size_t base = ((size_t)blockIdx.y * NN + blockIdx.x) * NN;
    float* row = g_S + base;
    int t = threadIdx.x;

    float vals[16];
    float m = -1e30f;
    #pragma unroll
    for (int u = 0; u < 16; u++) {
        vals[u] = row[t + u * 256];
        m = fmaxf(m, vals[u]);
    }
    red[t] = m;
    __syncthreads();
    for (int s = 128; s > 0; s >>= 1) {
        if (t < s) red[t] = fmaxf(red[t], red[t + s]);
        __syncthreads();
    }
    m = red[0];
    __syncthreads();

    float sum = 0.f;
    #pragma unroll
    for (int u = 0; u < 16; u++) {
        vals[u] = __expf(vals[u] - m);
        sum += vals[u];
    }
    red[t] = sum;
    __syncthreads();
    for (int s = 128; s > 0; s >>= 1) {
        if (t < s) red[t] += red[t + s];
        __syncthreads();
    }
    float inv = 1.0f / red[0];
    #pragma unroll
    for (int u = 0; u < 16; u++)
        row[t + u * 256] = vals[u] * inv;
}

// ---------------------------------------------------------------------------
// scores_out[b][j] = sum_i S[b][i][j]   (column sums, coalesced over j)
// ---------------------------------------------------------------------------
__global__ __launch_bounds__(256) void colsum_kernel(float* __restrict__ scores_out)
{
    int b = blockIdx.y;
    int j = blockIdx.x * 256 + threadIdx.x;
    const float* Sb = g_S + (size_t)b * NN * NN;
    float s = 0.f;
    for (int i = 0; i < NN; i++)
        s += Sb[(size_t)i * NN + j];
    scores_out[(size_t)b * NN + j] = s;
}

// ---------------------------------------------------------------------------
// Final output (d-major): out[b][d][t] = sum_j S[b][t][j] * V[b][j][d]
// Tile 64(t) x 64(d), k-chunk 16 over j.
// ---------------------------------------------------------------------------
__global__ __launch_bounds__(256) void o_kernel(float* __restrict__ out)
{
    int b = blockIdx.z;
    const float* S = g_S + (size_t)b * NN * NN;
    const float* V = &g_QKV[2][(size_t)b * NN * DD];
    float* O = out + (size_t)b * DD * NN;

    __shared__ float Ss[16][64 + 1];  // [kk(j)][tt]
    __shared__ float Vs[16][64 + 1];  // [kk(j)][dd]

    int t0 = blockIdx.x * 64;
    int d0 = blockIdx.y * 64;
    int tid = threadIdx.x;
    int tx = tid % 16;   // d micro
    int ty = tid / 16;   // t micro

    float acc[4][4] = {};   // [t][d]

    for (int j0 = 0; j0 < NN; j0 += 16) {
        // Ss[kk][tt] <- S[(t0+tt)*NN + j0+kk]  (contiguous over kk)
        {
            int tt = tid / 4;
            int kk = (tid % 4) * 4;
            float4 v = *(const float4*)&S[(size_t)(t0 + tt) * NN + j0 + kk];
            Ss[kk + 0][tt] = v.x; Ss[kk + 1][tt] = v.y;
            Ss[kk + 2][tt] = v.z; Ss[kk + 3][tt] = v.w;
        }
        // Vs[kk][dd] <- V[(j0+kk)*DD + d0+dd]  (contiguous over dd)
        {
            int f  = tid * 4;
            int kk = f / 64;
            int dd = f % 64;
            float4 v = *(const float4*)&V[(size_t)(j0 + kk) * DD + d0 + dd];
            Vs[kk][dd + 0] = v.x; Vs[kk][dd + 1] = v.y;
            Vs[kk][dd + 2] = v.z; Vs[kk][dd + 3] = v.w;
        }
        __syncthreads();

        #pragma unroll
        for (int kk = 0; kk < 16; kk++) {
            float a[4], c[4];
            #pragma unroll
            for (int u = 0; u < 4; u++) a[u] = Ss[kk][ty * 4 + u];
            #pragma unroll
            for (int v = 0; v < 4; v++) c[v] = Vs[kk][tx * 4 + v];
            #pragma unroll
            for (int u = 0; u < 4; u++)
                #pragma unroll
                for (int v = 0; v < 4; v++)
                    acc[u][v] += a[u] * c[v];
        }
        __syncthreads();
    }

    // O[(d0+dd)*NN + t0+tt] ; contiguous over tt -> vectorize over u
    #pragma unroll
    for (int v = 0; v < 4; v++) {
        float4 r = make_float4(acc[0][v], acc[1][v], acc[2][v], acc[3][v]);
        *(float4*)&O[(size_t)(d0 + tx * 4 + v) * NN + t0 + ty * 4] = r;
    }
}

// ---------------------------------------------------------------------------
extern "C" void kernel_launch(void* const* d_in, const int* in_sizes, int n_in,
                              void* d_out, int out_size)
{
    const float* x  = (const float*)d_in[0];
    const float* Wk = (const float*)d_in[1];
    const float* Wq = (const float*)d_in[2];
    const float* Wv = (const float*)d_in[3];

    float* out        = (float*)d_out;                       // (B, D, H, W)
    float* scores_out = out + (size_t)BB * DD * NN;          // (B, 1, H, W)

    qkv_kernel<<<dim3(NN / 64, DD / 64, BB * 3), 256>>>(x, Wq, Wk, Wv);
    s_kernel<<<dim3(NN / 64, NN / 64, BB), 256>>>();
    softmax_kernel<<<dim3(NN, BB), 256>>>();
    o_kernel<<<dim3(NN / 64, DD / 64, BB), 256>>>(out);
    colsum_kernel<<<dim3(NN / 256, BB), 256>>>(scores_out);
}

// round 3
// speedup vs baseline: 3.8477x; 3.8477x over previous
#include <cuda_runtime.h>
#include <math.h>
#include <stdint.h>

#define BB 4
#define CC 512
#define NN 4096   // H*W
#define DD 512
#define SCALE 0.04419417382415922f   // 1/sqrt(512)

// Scratch (__device__ globals; no allocation allowed)
__device__ float g_Xt[(size_t)BB * NN * CC];     // x transposed: [b][t][c]
__device__ float g_Q [(size_t)BB * NN * DD];     // [b][t][d]
__device__ float g_K [(size_t)BB * NN * DD];     // [b][t][d]
__device__ float g_Vt[(size_t)BB * DD * NN];     // [b][d][t]  (V transposed)
__device__ float g_S [(size_t)BB * NN * NN];     // [b][i][j]

// ---------------------------------------------------------------------------
// helpers
// ---------------------------------------------------------------------------
__device__ __forceinline__ uint32_t f2tf32(float x) {
    uint32_t r;
    asm("cvt.rna.tf32.f32 %0, %1;\n" : "=r"(r) : "f"(x));
    return r;
}

__device__ __forceinline__ void mma_tf32(float c[4],
    uint32_t a0, uint32_t a1, uint32_t a2, uint32_t a3,
    uint32_t b0, uint32_t b1)
{
    asm volatile(
        "mma.sync.aligned.m16n8k8.row.col.f32.tf32.tf32.f32 "
        "{%0,%1,%2,%3}, {%4,%5,%6,%7}, {%8,%9}, {%0,%1,%2,%3};\n"
        : "+f"(c[0]), "+f"(c[1]), "+f"(c[2]), "+f"(c[3])
        : "r"(a0), "r"(a1), "r"(a2), "r"(a3), "r"(b0), "r"(b1));
}

// ---------------------------------------------------------------------------
// x (B,C,N) -> Xt (B,N,C)
// ---------------------------------------------------------------------------
__global__ __launch_bounds__(256) void transpose_x(const float* __restrict__ x,
                                                   float* __restrict__ xt)
{
    __shared__ float tile[32][33];
    int b  = blockIdx.z;
    int t0 = blockIdx.x * 32;
    int c0 = blockIdx.y * 32;
    const float* in = x + (size_t)b * CC * NN;
    float* out = xt + (size_t)b * NN * CC;

    #pragma unroll
    for (int i = threadIdx.y; i < 32; i += 8)
        tile[i][threadIdx.x] = in[(size_t)(c0 + i) * NN + t0 + threadIdx.x];
    __syncthreads();
    #pragma unroll
    for (int i = threadIdx.y; i < 32; i += 8)
        out[(size_t)(t0 + i) * CC + c0 + threadIdx.x] = tile[threadIdx.x][i];
}

// ---------------------------------------------------------------------------
// Generic tf32 tensor-core GEMM:  C[m][n] = scale * sum_k A[m][k] * B[n][k]
// A row stride = K, B row stride = K, C row stride = N. Batched via grid.z.
// Block tile 128x128, k-tile 32, 256 threads (8 warps, 2x4 warp grid, 64x32
// warp tiles of m16n8k8 atoms). Register-double-buffered gmem loads.
// ---------------------------------------------------------------------------
#define LDK 36  // padded smem k-stride (words): banks (4r+c)%32 all distinct

__global__ __launch_bounds__(256, 1) void gemm_tc(
    const float* __restrict__ A, const float* __restrict__ B, float* __restrict__ C,
    int M, int N, int K,
    size_t sA, size_t sB, size_t sC, float scale)
{
    __shared__ uint32_t As[128 * LDK];
    __shared__ uint32_t Bs[128 * LDK];

    const float* Ab = A + blockIdx.z * sA + (size_t)(blockIdx.y * 128) * K;
    const float* Bb = B + blockIdx.z * sB + (size_t)(blockIdx.x * 128) * K;
    float* Cb = C + blockIdx.z * sC;
    int m0 = blockIdx.y * 128, n0 = blockIdx.x * 128;

    int tid  = threadIdx.x;
    int lane = tid & 31;
    int warp = tid >> 5;
    int wm = (warp >> 2) * 64;    // warp m offset (0,64)
    int wn = (warp & 3) * 32;     // warp n offset (0,32,64,96)

    float acc[4][4][4] = {};      // [m-atom][n-atom][frag]

    // gmem tile load mapping: 128 rows x 32 k per operand, float4 per thread x4
    int lr = tid >> 3;            // 0..31 (row group)
    int lk = (tid & 7) * 4;       // k offset 0..28

    float4 pa[4], pb[4];
    #pragma unroll
    for (int it = 0; it < 4; it++) {
        pa[it] = *(const float4*)&Ab[(size_t)(lr + it * 32) * K + lk];
        pb[it] = *(const float4*)&Bb[(size_t)(lr + it * 32) * K + lk];
    }

    for (int k0 = 0; k0 < K; k0 += 32) {
        // regs -> smem (convert to tf32)
        #pragma unroll
        for (int it = 0; it < 4; it++) {
            uint32_t* a = &As[(lr + it * 32) * LDK + lk];
            a[0] = f2tf32(pa[it].x); a[1] = f2tf32(pa[it].y);
            a[2] = f2tf32(pa[it].z); a[3] = f2tf32(pa[it].w);
            uint32_t* b = &Bs[(lr + it * 32) * LDK + lk];
            b[0] = f2tf32(pb[it].x); b[1] = f2tf32(pb[it].y);
            b[2] = f2tf32(pb[it].z); b[3] = f2tf32(pb[it].w);
        }
        __syncthreads();

        // prefetch next k-tile
        if (k0 + 32 < K) {
            #pragma unroll
            for (int it = 0; it < 4; it++) {
                pa[it] = *(const float4*)&Ab[(size_t)(lr + it * 32) * K + k0 + 32 + lk];
                pb[it] = *(const float4*)&Bb[(size_t)(lr + it * 32) * K + k0 + 32 + lk];
            }
        }

        int r = lane >> 2, c = lane & 3;
        #pragma unroll
        for (int kk = 0; kk < 32; kk += 8) {
            uint32_t af[4][4], bf[4][2];
            #pragma unroll
            for (int ma = 0; ma < 4; ma++) {
                int row = wm + ma * 16;
                af[ma][0] = As[(row + r)     * LDK + kk + c];
                af[ma][1] = As[(row + r + 8) * LDK + kk + c];
                af[ma][2] = As[(row + r)     * LDK + kk + c + 4];
                af[ma][3] = As[(row + r + 8) * LDK + kk + c + 4];
            }
            #pragma unroll
            for (int na = 0; na < 4; na++) {
                int col = wn + na * 8;
                bf[na][0] = Bs[(col + r) * LDK + kk + c];       // b0: k=lane%4, n=lane/4
                bf[na][1] = Bs[(col + r) * LDK + kk + c + 4];   // b1: k=lane%4+4
            }
            #pragma unroll
            for (int ma = 0; ma < 4; ma++)
                #pragma unroll
                for (int na = 0; na < 4; na++)
                    mma_tf32(acc[ma][na],
                             af[ma][0], af[ma][1], af[ma][2], af[ma][3],
                             bf[na][0], bf[na][1]);
        }
        __syncthreads();
    }

    // epilogue: c0 (r, 2c), c1 (r, 2c+1), c2 (r+8, 2c), c3 (r+8, 2c+1)
    int r = lane >> 2, cc = (lane & 3) * 2;
    #pragma unroll
    for (int ma = 0; ma < 4; ma++)
        #pragma unroll
        for (int na = 0; na < 4; na++) {
            int row = m0 + wm + ma * 16 + r;
            int col = n0 + wn + na * 8 + cc;
            float2 v0 = make_float2(acc[ma][na][0] * scale, acc[ma][na][1] * scale);
            float2 v1 = make_float2(acc[ma][na][2] * scale, acc[ma][na][3] * scale);
            *(float2*)&Cb[(size_t)row * N + col]       = v0;
            *(float2*)&Cb[(size_t)(row + 8) * N + col] = v1;
        }
}

// ---------------------------------------------------------------------------
// In-place row softmax over S
// ---------------------------------------------------------------------------
__global__ __launch_bounds__(256) void softmax_kernel()
{
    __shared__ float red[256];
    float* row = g_S + ((size_t)blockIdx.y * NN + blockIdx.x) * NN;
    int t = threadIdx.x;

    float vals[16];
    float m = -1e30f;
    #pragma unroll
    for (int u = 0; u < 16; u++) {
        vals[u] = row[t + u * 256];
        m = fmaxf(m, vals[u]);
    }
    red[t] = m;
    __syncthreads();
    for (int s = 128; s > 0; s >>= 1) {
        if (t < s) red[t] = fmaxf(red[t], red[t + s]);
        __syncthreads();
    }
    m = red[0];
    __syncthreads();

    float sum = 0.f;
    #pragma unroll
    for (int u = 0; u < 16; u++) {
        vals[u] = __expf(vals[u] - m);
        sum += vals[u];
    }
    red[t] = sum;
    __syncthreads();
    for (int s = 128; s > 0; s >>= 1) {
        if (t < s) red[t] += red[t + s];
        __syncthreads();
    }
    float inv = 1.0f / red[0];
    #pragma unroll
    for (int u = 0; u < 16; u++)
        row[t + u * 256] = vals[u] * inv;
}

// ---------------------------------------------------------------------------
// scores_out[b][j] = sum_i S[b][i][j], split over i with atomics
// ---------------------------------------------------------------------------
__global__ __launch_bounds__(256) void zero_scores(float* __restrict__ scores_out)
{
    int idx = blockIdx.x * 256 + threadIdx.x;
    if (idx < BB * NN) scores_out[idx] = 0.f;
}

__global__ __launch_bounds__(256) void colsum_kernel(float* __restrict__ scores_out)
{
    int b = blockIdx.z;
    int j = blockIdx.x * 256 + threadIdx.x;
    int i0 = blockIdx.y * 256;
    const float* Sb = g_S + (size_t)b * NN * NN;
    float s = 0.f;
    #pragma unroll 8
    for (int i = i0; i < i0 + 256; i++)
        s += Sb[(size_t)i * NN + j];
    atomicAdd(&scores_out[(size_t)b * NN + j], s);
}

// ---------------------------------------------------------------------------
extern "C" void kernel_launch(void* const* d_in, const int* in_sizes, int n_in,
                              void* d_out, int out_size)
{
    const float* x  = (const float*)d_in[0];
    const float* Wk = (const float*)d_in[1];
    const float* Wq = (const float*)d_in[2];
    const float* Wv = (const float*)d_in[3];

    float* out        = (float*)d_out;                 // (B, D, H, W) = [b][d][t]
    float* scores_out = out + (size_t)BB * DD * NN;    // (B, 1, H, W)

    float *Xt, *Q, *K, *Vt, *S;
    cudaGetSymbolAddress((void**)&Xt, g_Xt);
    cudaGetSymbolAddress((void**)&Q,  g_Q);
    cudaGetSymbolAddress((void**)&K,  g_K);
    cudaGetSymbolAddress((void**)&Vt, g_Vt);
    cudaGetSymbolAddress((void**)&S,  g_S);

    // 1) transpose x -> Xt[b][t][c]
    transpose_x<<<dim3(NN / 32, CC / 32, BB), dim3(32, 8)>>>(x, Xt);

    // 2) Q[t][d] = Xt . Wq^T   (M=N tokens, N=DD, K=CC)
    gemm_tc<<<dim3(DD / 128, NN / 128, BB), 256>>>(
        Xt, Wq, Q, NN, DD, CC,
        (size_t)NN * CC, 0, (size_t)NN * DD, 1.0f);
    // 3) K[t][d] = Xt . Wk^T
    gemm_tc<<<dim3(DD / 128, NN / 128, BB), 256>>>(
        Xt, Wk, K, NN, DD, CC,
        (size_t)NN * CC, 0, (size_t)NN * DD, 1.0f);
    // 4) Vt[d][t] = Wv . Xt^T   (operands swapped -> transposed V for free)
    gemm_tc<<<dim3(NN / 128, DD / 128, BB), 256>>>(
        Wv, Xt, Vt, DD, NN, CC,
        0, (size_t)NN * CC, (size_t)DD * NN, 1.0f);

    // 5) S[i][j] = SCALE * Q . K^T
    gemm_tc<<<dim3(NN / 128, NN / 128, BB), 256>>>(
        Q, K, S, NN, NN, DD,
        (size_t)NN * DD, (size_t)NN * DD, (size_t)NN * NN, SCALE);

    // 6) softmax rows of S in place
    softmax_kernel<<<dim3(NN, BB), 256>>>();

    // 7) out[d][t] = Vt . S^T  (K = tokens j)
    gemm_tc<<<dim3(NN / 128, DD / 128, BB), 256>>>(
        Vt, S, out, DD, NN, NN,
        (size_t)DD * NN, (size_t)NN * NN, (size_t)DD * NN, 1.0f);

    // 8) scores_out[b][j] = sum_i S[b][i][j]
    zero_scores<<<(BB * NN + 255) / 256, 256>>>(scores_out);
    colsum_kernel<<<dim3(NN / 256, NN / 256, BB), 256>>>(scores_out);
}